// round 4
// baseline (speedup 1.0000x reference)
#include <cuda_runtime.h>
#include <cuda_bf16.h>

// out[b,i,j] = softmax_j( exp( exp(-||x_bi - x_bj||^2 * p) ) ), B=128, K=1024.
//
// R4: kill the per-element LDS (R3 profile: L1 65% = binding).
//  - Block = (b, 16-row tile), 512 threads / 16 warps, grid 8192.
//  - Warp w owns 64 COLUMNS: lane holds c-points j = w*64+lane*2, +1 in
//    REGISTERS (loaded once). Row loop broadcasts one point per row (cheap
//    conflict-free broadcast LDS). LDS traffic: 2 GB -> ~0.
//  - exp(exp(-d*p)) with 2 EX2 and NO scalar muls between them:
//      arg  = (||a||^2 + ||c||^2 - 2 a.c) * (-p*log2e) + log2(log2e)
//      A'   = 2^arg  ( = log2e * exp(-d*p) )
//      e    = 2^A'   ( = exp(exp(-d*p)) exactly, modulo ex2 approx )
//  - v[2][16] in registers across sum -> normalize; exp evaluated once.
//  - Row sums: warp shuffle reduce -> smem [16][16] -> 16 threads invert.

static constexpr int K = 1024;
static constexpr int THREADS = 512;
static constexpr int ROWS = 16;
static constexpr float LOG2E = 1.4426950408889634f;
static constexpr float LOG2_LOG2E = 0.5287663729448977f;  // log2(log2(e))

__device__ __forceinline__ float ex2f(float x) {
    float r;
    asm("ex2.approx.f32 %0, %1;" : "=f"(r) : "f"(x));
    return r;
}

__global__ void __launch_bounds__(THREADS, 2)
adjacency_softmax_kernel(const float* __restrict__ coords,
                         const float* __restrict__ prec,
                         float* __restrict__ out)
{
    __shared__ float4 pk[K];            // (x, y, z, ||x||^2 * q), q = -p*log2e
    __shared__ float  wsum[ROWS][16];   // per-warp partial row sums
    __shared__ float  inv_s[ROWS];

    const int b    = blockIdx.x >> 6;
    const int row0 = (blockIdx.x & 63) << 4;
    const int tid  = threadIdx.x;

    const float p = prec[0];
    const float q = -p * LOG2E;

    const float* cb = coords + (size_t)b * K * 3;
    #pragma unroll
    for (int j = tid; j < K; j += THREADS) {
        float x = cb[j * 3 + 0];
        float y = cb[j * 3 + 1];
        float z = cb[j * 3 + 2];
        pk[j] = make_float4(x, y, z, (x * x + y * y + z * z) * q);
    }
    __syncthreads();

    const int wid  = tid >> 5;
    const int lane = tid & 31;
    const int jb   = (wid << 6) + (lane << 1);   // 2 consecutive columns/lane

    const float4 c0 = pk[jb + 0];       // column points: registers, loaded once
    const float4 c1 = pk[jb + 1];
    const float  s2 = -2.0f * q;        // +2*p*log2e

    float v0[ROWS], v1[ROWS];

    #pragma unroll
    for (int r = 0; r < ROWS; r++) {
        const float4 a = pk[row0 + r];              // broadcast LDS (once/row)
        const float awc = a.w + LOG2_LOG2E;

        float d0 = a.x * c0.x;
        float d1 = a.x * c1.x;
        d0 = fmaf(a.y, c0.y, d0);
        d1 = fmaf(a.y, c1.y, d1);
        d0 = fmaf(a.z, c0.z, d0);
        d1 = fmaf(a.z, c1.z, d1);

        const float arg0 = fmaf(d0, s2, awc + c0.w);
        const float arg1 = fmaf(d1, s2, awc + c1.w);

        const float e0 = ex2f(ex2f(arg0));          // exp(exp(-d*p))
        const float e1 = ex2f(ex2f(arg1));
        v0[r] = e0;
        v1[r] = e1;

        float s = e0 + e1;
        #pragma unroll
        for (int o = 16; o > 0; o >>= 1)
            s += __shfl_xor_sync(0xFFFFFFFFu, s, o);
        if (lane == 0) wsum[r][wid] = s;
    }

    __syncthreads();

    if (tid < ROWS) {
        float s = 0.0f;
        #pragma unroll
        for (int w = 0; w < 16; w++) s += wsum[tid][w];
        inv_s[tid] = __fdividef(1.0f, s);
    }
    __syncthreads();

    float* __restrict__ ob = out + ((size_t)b * K + row0) * K + jb;

    #pragma unroll
    for (int r = 0; r < ROWS; r++) {
        const float inv = inv_s[r];                 // broadcast LDS
        float2 res = make_float2(v0[r] * inv, v1[r] * inv);
        *reinterpret_cast<float2*>(ob + (size_t)r * K) = res;   // STG.64
    }
}

extern "C" void kernel_launch(void* const* d_in, const int* in_sizes, int n_in,
                              void* d_out, int out_size)
{
    const float* coords = (const float*)d_in[0];   // [128, 1024, 3] f32
    const float* prec   = (const float*)d_in[1];   // [1] f32
    float* out          = (float*)d_out;           // [128, 1024, 1024] f32

    dim3 grid(128 * (K / ROWS));   // 8192 blocks
    adjacency_softmax_kernel<<<grid, THREADS>>>(coords, prec, out);
}

// round 5
// speedup vs baseline: 1.3263x; 1.3263x over previous
#include <cuda_runtime.h>
#include <cuda_bf16.h>

// out[b,i,j] = softmax_j( exp( exp(-||x_bi - x_bj||^2 * p) ) ), B=128, K=1024.
//
// R5: R4's register-resident columns, but the cross-lane reduction moves
// OUT of the row loop (R4 regression: 16x dependent 5-stage SHFL chains).
//  - Block = (b, 16-row tile), 512 threads / 16 warps, grid 8192.
//  - Warp w owns 64 columns; lane holds c-points jb, jb+1 in registers.
//  - Row loop: broadcast LDS of a-point, 8 fma-ops, 2x2 EX2. No shuffles.
//  - Post-loop butterfly: array-halving select+shuffle, 16 SHFL total/warp,
//    lane bit-reversal gives the row index; per-warp sums -> smem -> 16
//    threads invert -> normalize + STG.64.

static constexpr int K = 1024;
static constexpr int THREADS = 512;
static constexpr int ROWS = 16;
static constexpr float LOG2E = 1.4426950408889634f;
static constexpr float LOG2_LOG2E = 0.5287663729448977f;  // log2(log2(e))

__device__ __forceinline__ float ex2f(float x) {
    float r;
    asm("ex2.approx.f32 %0, %1;" : "=f"(r) : "f"(x));
    return r;
}

__global__ void __launch_bounds__(THREADS, 2)
adjacency_softmax_kernel(const float* __restrict__ coords,
                         const float* __restrict__ prec,
                         float* __restrict__ out)
{
    __shared__ float4 pk[K];            // (x, y, z, ||x||^2 * q), q = -p*log2e
    __shared__ float  wsum[ROWS][16];   // per-warp full row sums
    __shared__ float  inv_s[ROWS];

    const int b    = blockIdx.x >> 6;
    const int row0 = (blockIdx.x & 63) << 4;
    const int tid  = threadIdx.x;

    const float p = prec[0];
    const float q = -p * LOG2E;

    const float* cb = coords + (size_t)b * K * 3;
    #pragma unroll
    for (int j = tid; j < K; j += THREADS) {
        float x = cb[j * 3 + 0];
        float y = cb[j * 3 + 1];
        float z = cb[j * 3 + 2];
        pk[j] = make_float4(x, y, z, (x * x + y * y + z * z) * q);
    }
    __syncthreads();

    const int wid  = tid >> 5;
    const int lane = tid & 31;
    const int jb   = (wid << 6) + (lane << 1);   // 2 consecutive columns/lane

    const float4 c0 = pk[jb + 0];       // column points: registers, loaded once
    const float4 c1 = pk[jb + 1];
    const float  s2 = -2.0f * q;        // +2*p*log2e
    const float  cw0 = c0.w + LOG2_LOG2E;
    const float  cw1 = c1.w + LOG2_LOG2E;

    float v0[ROWS], v1[ROWS];

    #pragma unroll
    for (int r = 0; r < ROWS; r++) {
        const float4 a = pk[row0 + r];              // broadcast LDS (once/row)

        float d0 = a.x * c0.x;
        float d1 = a.x * c1.x;
        d0 = fmaf(a.y, c0.y, d0);
        d1 = fmaf(a.y, c1.y, d1);
        d0 = fmaf(a.z, c0.z, d0);
        d1 = fmaf(a.z, c1.z, d1);

        const float arg0 = fmaf(d0, s2, a.w + cw0);
        const float arg1 = fmaf(d1, s2, a.w + cw1);

        v0[r] = ex2f(ex2f(arg0));                   // exp(exp(-d*p))
        v1[r] = ex2f(ex2f(arg1));
    }

    // ---- Deferred cross-lane reduction: array-halving butterfly ----
    float s[ROWS];
    #pragma unroll
    for (int r = 0; r < ROWS; r++) s[r] = v0[r] + v1[r];

    #pragma unroll
    for (int stage = 0; stage < 4; stage++) {
        const int m = 1 << stage;        // xor mask
        const int h = 8 >> stage;        // surviving half-size: 8,4,2,1
        const bool up = (lane & m) != 0;
        #pragma unroll
        for (int r = 0; r < h; r++) {
            const float x = up ? s[r + h] : s[r];
            const float y = up ? s[r]     : s[r + h];
            s[r] = x + __shfl_xor_sync(0xFFFFFFFFu, y, m);
        }
    }
    // s[0] on lane l = sum over l's 16-lane half of row bitrev4(l & 15)
    {
        float t = s[0] + __shfl_xor_sync(0xFFFFFFFFu, s[0], 16);
        if (lane < 16) {
            const int row = ((lane & 1) << 3) | ((lane & 2) << 1) |
                            ((lane & 4) >> 1) | ((lane & 8) >> 3);
            wsum[row][wid] = t;
        }
    }
    __syncthreads();

    if (tid < ROWS) {
        float acc = 0.0f;
        #pragma unroll
        for (int w = 0; w < 16; w++) acc += wsum[tid][w];
        inv_s[tid] = __fdividef(1.0f, acc);
    }
    __syncthreads();

    float* __restrict__ ob = out + ((size_t)b * K + row0) * K + jb;

    #pragma unroll
    for (int r = 0; r < ROWS; r++) {
        const float inv = inv_s[r];                 // broadcast LDS
        float2 res = make_float2(v0[r] * inv, v1[r] * inv);
        *reinterpret_cast<float2*>(ob + (size_t)r * K) = res;   // STG.64
    }
}

extern "C" void kernel_launch(void* const* d_in, const int* in_sizes, int n_in,
                              void* d_out, int out_size)
{
    const float* coords = (const float*)d_in[0];   // [128, 1024, 3] f32
    const float* prec   = (const float*)d_in[1];   // [1] f32
    float* out          = (float*)d_out;           // [128, 1024, 1024] f32

    dim3 grid(128 * (K / ROWS));   // 8192 blocks
    adjacency_softmax_kernel<<<grid, THREADS>>>(coords, prec, out);
}